// round 3
// baseline (speedup 1.0000x reference)
#include <cuda_runtime.h>
#include <cstdint>

// PatchSampler: out[b,c,i,j] = bchw[b, c, iy[j], ix[i]], nearest = round-half-
// even of (center-16+k-0.5) = (center-16+k) & ~1, zero padding outside 1024^2.
//
// Round 3: 4 outputs (a j-quad) per thread. For 4 consecutive j the even-floor
// rows collapse to 3 distinct loads:
//   n0 even: rows {n0, n0, n0+2, n0+2}      -> o2 takes row iy3
//   n0 odd : rows {n0-1, n0+1, n0+1, n0+3}  -> o2 takes row iy1
// Store is one coalesced STG.128 per thread. This cuts L1tex line-wavefronts
// per CTA ~2.7x and LDG issues 4x vs the scalar version.

#define PS_C  128
#define PS_HW 1024
#define PS_R  16

__global__ __launch_bounds__(256, 8)
void patch_sampler_kernel(const float* __restrict__ bchw,
                          const int*   __restrict__ centers,
                          float4*      __restrict__ out4)
{
    const int bc = blockIdx.x;            // 0 .. 255
    const int b  = bc >> 7;
    const int c  = bc & 127;

    const int cx = __ldg(&centers[b * (2 * PS_C) + c]);
    const int cy = __ldg(&centers[b * (2 * PS_C) + PS_C + c]);

    const int t  = threadIdx.x;           // 0 .. 255
    const int i  = t >> 3;                // 0 .. 31  (output dim 2)
    const int j0 = (t & 7) << 2;          // 0,4,...,28 (output dim 3 quad)

    const int ix = (cx - PS_R + i) & ~1;
    const bool xok = (unsigned)ix < (unsigned)PS_HW;

    const int n0  = cy - PS_R + j0;
    const int iy0 = n0 & ~1;              // row for j0
    const int iy1 = (n0 + 1) & ~1;        // row for j0+1 (== row for j0+2 iff n0 odd)
    const int iy3 = (n0 + 3) & ~1;        // row for j0+3 (== row for j0+2 iff n0 even)
    const bool odd = (n0 & 1) != 0;       // uniform across block (parity of cy)

    const float* __restrict__ img = bchw + ((size_t)bc << 20) + ix;

    float v0 = 0.0f, v1 = 0.0f, v3 = 0.0f;
    if (xok) {
        if ((unsigned)iy0 < (unsigned)PS_HW) v0 = __ldg(img + ((size_t)iy0 << 10));
        if ((unsigned)iy1 < (unsigned)PS_HW) v1 = __ldg(img + ((size_t)iy1 << 10));
        if ((unsigned)iy3 < (unsigned)PS_HW) v3 = __ldg(img + ((size_t)iy3 << 10));
    }

    float4 o;
    o.x = v0;
    o.y = v1;
    o.z = odd ? v1 : v3;
    o.w = v3;

    // out element index = bc*1024 + i*32 + j0 ; /4 for float4 = bc*256 + t
    out4[((size_t)bc << 8) + t] = o;      // coalesced STG.128
}

extern "C" void kernel_launch(void* const* d_in, const int* in_sizes, int n_in,
                              void* d_out, int out_size)
{
    const float* bchw    = (const float*)d_in[0];
    const int*   centers = (const int*)d_in[1];
    float4*      out4    = (float4*)d_out;

    patch_sampler_kernel<<<2 * PS_C, 256>>>(bchw, centers, out4);
}